// round 1
// baseline (speedup 1.0000x reference)
#include <cuda_runtime.h>

#define NN 50000
#define DD 64
#define EE 800000

// ---- scratch (device globals; no runtime allocation allowed) ----
__device__ float g_h[4ull * NN * DD];        // 51.2 MB  h = x@W per param set
__device__ float g_s[4 * NN];                // per-node src score
__device__ float g_d[4 * NN];                // per-node dst score
__device__ int   g_cnt[8 * NN];              // per-(conv,node) incoming-edge count
__device__ int2  g_ebuf[8ull * NN * 64];     // 204.8 MB  {src, w-as-int} records, 64 slots/node

// conv c (input-edge order: tp_a,tp_b,tn_a,tn_b,dp_a,dp_b,dn_a,dn_b) -> output slot
__constant__ int c_omap[8] = {0, 1, 4, 5, 2, 3, 6, 7};

struct EdgePtrs { const int* e[8]; };

// ---------------------------------------------------------------------------
// Kernel 1: h = x @ W[p]; s = h.a_src; d = h.a_dst; zero counters.
// grid = (ceil(N/64), 4), block = 64 threads (thread-per-row, 64 fp32 accs)
// ---------------------------------------------------------------------------
__global__ void gemm_kernel(const float* __restrict__ x, const float* __restrict__ W,
                            const float* __restrict__ asrc, const float* __restrict__ adst) {
    __shared__ float Ws[64 * 64];
    __shared__ float av[64], bv[64];
    __shared__ float xs[64 * 65];           // +1 pad: conflict-free strided access

    const int p    = blockIdx.y;
    const int row0 = blockIdx.x * 64;
    const int tid  = threadIdx.x;           // 0..63

    for (int idx = tid; idx < 4096; idx += 64) Ws[idx] = W[p * 4096 + idx];
    av[tid] = asrc[p * 64 + tid];
    bv[tid] = adst[p * 64 + tid];
    for (int m = 0; m < 64; m++) {
        int grow = row0 + m;
        xs[m * 65 + tid] = (grow < NN) ? x[grow * 64 + tid] : 0.f;
    }
    __syncthreads();

    float acc[64];
#pragma unroll
    for (int j = 0; j < 64; j++) acc[j] = 0.f;

    const float4* W4 = (const float4*)Ws;
#pragma unroll 2
    for (int k = 0; k < 64; k++) {
        float xv = xs[tid * 65 + k];
        const float4* wr = W4 + k * 16;
#pragma unroll
        for (int j4 = 0; j4 < 16; j4++) {
            float4 w = wr[j4];
            acc[4 * j4 + 0] = fmaf(xv, w.x, acc[4 * j4 + 0]);
            acc[4 * j4 + 1] = fmaf(xv, w.y, acc[4 * j4 + 1]);
            acc[4 * j4 + 2] = fmaf(xv, w.z, acc[4 * j4 + 2]);
            acc[4 * j4 + 3] = fmaf(xv, w.w, acc[4 * j4 + 3]);
        }
    }

    float sv = 0.f, dv = 0.f;
#pragma unroll
    for (int j = 0; j < 64; j++) {
        sv = fmaf(acc[j], av[j], sv);
        dv = fmaf(acc[j], bv[j], dv);
    }

    // stage h through smem for coalesced global write
    __syncthreads();
#pragma unroll
    for (int j = 0; j < 64; j++) xs[tid * 65 + j] = acc[j];
    __syncthreads();

    float* hout = g_h + ((size_t)p * NN + row0) * 64;
    int rmax = NN - row0; if (rmax > 64) rmax = 64;
    for (int m = 0; m < rmax; m++)
        hout[m * 64 + tid] = xs[m * 65 + tid];

    int i = row0 + tid;
    if (i < NN) {
        g_s[p * NN + i] = sv;
        g_d[p * NN + i] = dv;
        g_cnt[(2 * p) * NN + i]     = 0;
        g_cnt[(2 * p + 1) * NN + i] = 0;
    }
}

// ---------------------------------------------------------------------------
// Kernel 2: bucket every (non-self) edge by dst; record {src, exp(leakyrelu(e))}.
// grid = (E/256, 8), block = 256
// ---------------------------------------------------------------------------
__global__ void scatter_kernel(EdgePtrs ep) {
    const int c = blockIdx.y;
    const int r = blockIdx.x * blockDim.x + threadIdx.x;
    if (r >= EE) return;
    const int* __restrict__ e = ep.e[c];
    int src = __ldg(e + r);
    int dst = __ldg(e + EE + r);
    if (src == dst) return;                       // masked to -1e9 in ref -> exp()==0 exactly
    const int p = c >> 1;
    float t  = __ldg(g_s + p * NN + src) + __ldg(g_d + p * NN + dst);
    float lr = (t > 0.f) ? t : 0.2f * t;          // leaky_relu, slope 0.2
    float wv = expf(lr);                          // no max-sub needed: |t| <~ 10
    int slot = atomicAdd(g_cnt + c * NN + dst, 1);
    if (slot < 64)
        g_ebuf[(((size_t)c * NN + dst) << 6) + slot] = make_int2(src, __float_as_int(wv));
}

// ---------------------------------------------------------------------------
// Kernel 3: warp per (conv, node): softmax denom in-warp, aggregate h rows,
// add bias, relu, write output slot. Zero atomics.
// grid = 50000 blocks x 256 threads (8 warps/block), 400000 warps total.
// ---------------------------------------------------------------------------
__global__ void gather_kernel(const float* __restrict__ bias, float* __restrict__ out) {
    const int wid  = blockIdx.x * (blockDim.x >> 5) + (threadIdx.x >> 5);
    const int lane = threadIdx.x & 31;
    if (wid >= 8 * NN) return;
    const int c = wid / NN;
    const int i = wid - c * NN;
    const int p = c >> 1;
    const int o = c_omap[c];

    int n = g_cnt[c * NN + i];
    n = (n > 64) ? 64 : n;

    // self-loop term (always present)
    float t = g_s[p * NN + i] + g_d[p * NN + i];
    float wself = expf(t > 0.f ? t : 0.2f * t);

    const int2* eb = g_ebuf + (((size_t)c * NN + i) << 6);
    int2 r1 = make_int2(0, 0), r2 = make_int2(0, 0);
    if (lane < n)      r1 = __ldg(eb + lane);
    if (lane + 32 < n) r2 = __ldg(eb + lane + 32);

    // denom = wself + sum of all edge weights (lane-parallel + butterfly reduce)
    float wsum = __int_as_float(r1.y) + __int_as_float(r2.y);
#pragma unroll
    for (int off = 16; off; off >>= 1) wsum += __shfl_xor_sync(0xffffffffu, wsum, off);
    float inv = 1.f / (wself + wsum);

    const float2* __restrict__ h2 = (const float2*)g_h;
    // self-loop contribution
    float2 hv = h2[((size_t)p * NN + i) * 32 + lane];
    float a0 = wself * inv;
    float ax = a0 * hv.x, ay = a0 * hv.y;

#pragma unroll 4
    for (int k = 0; k < n; k++) {
        int sxk = (k < 32) ? r1.x : r2.x;       // k uniform across warp
        int wyk = (k < 32) ? r1.y : r2.y;
        int   sk = __shfl_sync(0xffffffffu, sxk, k & 31);
        float wk = __int_as_float(__shfl_sync(0xffffffffu, wyk, k & 31));
        float2 hh = h2[((size_t)p * NN + sk) * 32 + lane];
        float al = wk * inv;
        ax = fmaf(al, hh.x, ax);
        ay = fmaf(al, hh.y, ay);
    }

    float2 bb = ((const float2*)bias)[p * 32 + lane];
    ax = fmaxf(ax + bb.x, 0.f);
    ay = fmaxf(ay + bb.y, 0.f);
    ((float2*)out)[((size_t)o * NN + i) * 32 + lane] = make_float2(ax, ay);
}

// ---------------------------------------------------------------------------
extern "C" void kernel_launch(void* const* d_in, const int* in_sizes, int n_in,
                              void* d_out, int out_size) {
    (void)in_sizes; (void)n_in; (void)out_size;
    const float* x    = (const float*)d_in[8];
    const float* W    = (const float*)d_in[9];
    const float* asrc = (const float*)d_in[10];
    const float* adst = (const float*)d_in[11];
    const float* bias = (const float*)d_in[12];

    EdgePtrs ep;
    for (int i = 0; i < 8; i++) ep.e[i] = (const int*)d_in[i];

    dim3 ggrid((NN + 63) / 64, 4);
    gemm_kernel<<<ggrid, 64>>>(x, W, asrc, adst);

    dim3 sgrid((EE + 255) / 256, 8);
    scatter_kernel<<<sgrid, 256>>>(ep);

    gather_kernel<<<(8 * NN + 7) / 8, 256>>>(bias, (float*)d_out);
}

// round 2
// speedup vs baseline: 1.1648x; 1.1648x over previous
#include <cuda_runtime.h>

#define NN 50000
#define DD 64
#define EE 800000

// ---- scratch (device globals; no runtime allocation allowed) ----
__device__ float g_h[4ull * NN * DD];        // 51.2 MB  h = x@W per param set
__device__ float g_s[4 * NN];                // per-node src score  s = x.(W a_src)
__device__ float g_d[4 * NN];                // per-node dst score
__device__ float g_ws[4 * 64];               // W @ a_src  per param set
__device__ float g_wd[4 * 64];               // W @ a_dst
__device__ int   g_cnt[8 * NN];              // per-(conv,node) incoming-edge count
__device__ int   g_ebuf[8ull * NN * 64];     // 102.4 MB  src-only records, 64 slots/node

// conv c (edge input order: tp_a,tp_b,tn_a,tn_b,dp_a,dp_b,dn_a,dn_b) -> output slot
__constant__ int c_omap[8] = {0, 1, 4, 5, 2, 3, 6, 7};

struct EdgePtrs { const int* e[8]; };

// ---------------------------------------------------------------------------
// Kernel 0: ws = W @ a_src, wd = W @ a_dst (tiny).  grid=4, block=64.
// ---------------------------------------------------------------------------
__global__ void prep_kernel(const float* __restrict__ W,
                            const float* __restrict__ asrc,
                            const float* __restrict__ adst) {
    const int p = blockIdx.x, k = threadIdx.x;
    const float* Wr = W + p * 4096 + k * 64;
    float a = 0.f, b = 0.f;
#pragma unroll 8
    for (int j = 0; j < 64; j++) {
        float w = Wr[j];
        a = fmaf(w, __ldg(asrc + p * 64 + j), a);
        b = fmaf(w, __ldg(adst + p * 64 + j), b);
    }
    g_ws[p * 64 + k] = a;
    g_wd[p * 64 + k] = b;
}

// ---------------------------------------------------------------------------
// Kernel 1: s[p][i] = x_i . ws[p],  d[p][i] = x_i . wd[p]; also zero g_cnt.
// grid = (ceil(N/8), 4), block = 256 (warp per node).
// ---------------------------------------------------------------------------
__global__ void score_kernel(const float* __restrict__ x) {
    const int p = blockIdx.y;
    if (p == 0) {   // zero counters: 6250*256 = 1.6M threads >= 400k entries
        int z = blockIdx.x * blockDim.x + threadIdx.x;
        if (z < 8 * NN) g_cnt[z] = 0;
    }
    const int warp = threadIdx.x >> 5, lane = threadIdx.x & 31;
    const int i = blockIdx.x * 8 + warp;
    if (i >= NN) return;
    float2 xv = ((const float2*)x)[(size_t)i * 32 + lane];
    float2 wa = ((const float2*)g_ws)[p * 32 + lane];
    float2 wb = ((const float2*)g_wd)[p * 32 + lane];
    float sa = xv.x * wa.x + xv.y * wa.y;
    float sb = xv.x * wb.x + xv.y * wb.y;
#pragma unroll
    for (int o = 16; o; o >>= 1) {
        sa += __shfl_xor_sync(0xffffffffu, sa, o);
        sb += __shfl_xor_sync(0xffffffffu, sb, o);
    }
    if (lane == 0) { g_s[p * NN + i] = sa; g_d[p * NN + i] = sb; }
}

// ---------------------------------------------------------------------------
// Kernel 2: bucket every (non-self) edge by dst; record src only (4B).
// grid = (E/256, 8), block = 256
// ---------------------------------------------------------------------------
__global__ void scatter_kernel(EdgePtrs ep) {
    const int c = blockIdx.y;
    const int r = blockIdx.x * blockDim.x + threadIdx.x;
    if (r >= EE) return;
    const int* __restrict__ e = ep.e[c];
    int src = __ldg(e + r);
    int dst = __ldg(e + EE + r);
    if (src == dst) return;                 // ref masks self edges to -1e9 -> weight 0
    int slot = atomicAdd(g_cnt + c * NN + dst, 1);
    if (slot < 64)
        g_ebuf[(((size_t)c * NN + dst) << 6) + slot] = src;
}

// ---------------------------------------------------------------------------
// Kernel 3: h = x @ W[p].  block = 256 (8 warps), 64 rows/block, warp -> 8 rows,
// lane -> cols {2*lane, 2*lane+1}.  grid = (ceil(N/64), 4).
// ---------------------------------------------------------------------------
__global__ void __launch_bounds__(256) gemm_kernel(const float* __restrict__ x,
                                                   const float* __restrict__ W) {
    __shared__ float Ws[64 * 64];            // 16 KB
    __shared__ float xs[64 * 68];            // 17.4 KB (68-stride: float4-aligned, pad)
    const int p    = blockIdx.y;
    const int row0 = blockIdx.x * 64;
    const int tid  = threadIdx.x;

    {   // load W (1024 float4, coalesced)
        const float4* W4 = (const float4*)(W + p * 4096);
        float4* Ws4 = (float4*)Ws;
        Ws4[tid]       = W4[tid];
        Ws4[tid + 256] = W4[tid + 256];
        Ws4[tid + 512] = W4[tid + 512];
        Ws4[tid + 768] = W4[tid + 768];
    }
    // load 64 x-rows (float4, coalesced)
#pragma unroll
    for (int q = tid; q < 1024; q += 256) {
        int r = q >> 4, c4 = q & 15;
        int grow = row0 + r;
        float4 v = (grow < NN) ? ((const float4*)x)[(size_t)grow * 16 + c4]
                               : make_float4(0.f, 0.f, 0.f, 0.f);
        *(float4*)&xs[r * 68 + c4 * 4] = v;
    }
    __syncthreads();

    const int warp = tid >> 5, lane = tid & 31;
    const int r0 = warp * 8;
    float2 acc[8];
#pragma unroll
    for (int r = 0; r < 8; r++) acc[r] = make_float2(0.f, 0.f);

    const float2* Ws2 = (const float2*)Ws;
#pragma unroll 4
    for (int k = 0; k < 64; k += 4) {
        float2 w0 = Ws2[(k + 0) * 32 + lane];
        float2 w1 = Ws2[(k + 1) * 32 + lane];
        float2 w2 = Ws2[(k + 2) * 32 + lane];
        float2 w3 = Ws2[(k + 3) * 32 + lane];
#pragma unroll
        for (int r = 0; r < 8; r++) {
            float4 xv = *(const float4*)&xs[(r0 + r) * 68 + k];
            acc[r].x = fmaf(xv.x, w0.x, acc[r].x); acc[r].y = fmaf(xv.x, w0.y, acc[r].y);
            acc[r].x = fmaf(xv.y, w1.x, acc[r].x); acc[r].y = fmaf(xv.y, w1.y, acc[r].y);
            acc[r].x = fmaf(xv.z, w2.x, acc[r].x); acc[r].y = fmaf(xv.z, w2.y, acc[r].y);
            acc[r].x = fmaf(xv.w, w3.x, acc[r].x); acc[r].y = fmaf(xv.w, w3.y, acc[r].y);
        }
    }

    float2* hp = (float2*)(g_h + (size_t)p * NN * 64);
#pragma unroll
    for (int r = 0; r < 8; r++) {
        int grow = row0 + r0 + r;
        if (grow < NN) hp[(size_t)grow * 32 + lane] = acc[r];   // 256B coalesced/row
    }
}

// ---------------------------------------------------------------------------
// Kernel 4: warp per (conv, node). Weights computed lane-parallel (MUFU exp),
// broadcast via per-warp smem, normalize once at the end. Zero atomics.
// grid = (ceil(N/8), 8), block = 256.
// ---------------------------------------------------------------------------
__global__ void __launch_bounds__(256) gather_kernel(const float* __restrict__ bias,
                                                     float* __restrict__ out) {
    __shared__ int2 rec[8][64];
    const int c    = blockIdx.y;
    const int warp = threadIdx.x >> 5, lane = threadIdx.x & 31;
    const int i    = blockIdx.x * 8 + warp;
    if (i >= NN) return;
    const int p = c >> 1;
    const int o = c_omap[c];

    int n = g_cnt[c * NN + i];
    if (n > 64) n = 64;

    const int*   eb  = g_ebuf + (((size_t)c * NN + i) << 6);
    const float* sp  = g_s + p * NN;
    const float  d_i = __ldg(g_d + p * NN + i);

    float w1 = 0.f, w2 = 0.f;
    int   s1 = 0,   s2 = 0;
    if (lane < n) {
        s1 = __ldg(eb + lane);
        float t = __ldg(sp + s1) + d_i;
        t = t > 0.f ? t : 0.2f * t;
        w1 = __expf(t);
    }
    if (lane + 32 < n) {
        s2 = __ldg(eb + lane + 32);
        float t = __ldg(sp + s2) + d_i;
        t = t > 0.f ? t : 0.2f * t;
        w2 = __expf(t);
    }
    rec[warp][lane] = make_int2(s1, __float_as_int(w1));
    if (n > 32) rec[warp][lane + 32] = make_int2(s2, __float_as_int(w2));
    __syncwarp();

    float tself = __ldg(sp + i) + d_i;
    tself = tself > 0.f ? tself : 0.2f * tself;
    const float wself = __expf(tself);

    float wsum = w1 + w2;
#pragma unroll
    for (int off = 16; off; off >>= 1) wsum += __shfl_xor_sync(0xffffffffu, wsum, off);
    const float inv = 1.f / (wself + wsum);

    const float2* __restrict__ h2 = (const float2*)g_h;
    const size_t hbase = (size_t)p * NN;
    float2 hv = h2[(hbase + i) * 32 + lane];
    float ax = wself * hv.x, ay = wself * hv.y;

#pragma unroll 4
    for (int k = 0; k < n; k++) {
        int2 rr = rec[warp][k];                         // LDS.64 broadcast
        float2 hh = h2[(hbase + rr.x) * 32 + lane];     // 256B coalesced row read
        float wk = __int_as_float(rr.y);
        ax = fmaf(wk, hh.x, ax);
        ay = fmaf(wk, hh.y, ay);
    }

    float2 bb = ((const float2*)bias)[p * 32 + lane];
    ax = fmaxf(fmaf(ax, inv, bb.x), 0.f);
    ay = fmaxf(fmaf(ay, inv, bb.y), 0.f);
    ((float2*)out)[((size_t)o * NN + i) * 32 + lane] = make_float2(ax, ay);
}

// ---------------------------------------------------------------------------
extern "C" void kernel_launch(void* const* d_in, const int* in_sizes, int n_in,
                              void* d_out, int out_size) {
    (void)in_sizes; (void)n_in; (void)out_size;
    const float* x    = (const float*)d_in[8];
    const float* W    = (const float*)d_in[9];
    const float* asrc = (const float*)d_in[10];
    const float* adst = (const float*)d_in[11];
    const float* bias = (const float*)d_in[12];

    EdgePtrs ep;
    for (int i = 0; i < 8; i++) ep.e[i] = (const int*)d_in[i];

    prep_kernel<<<4, 64>>>(W, asrc, adst);

    dim3 qgrid((NN + 7) / 8, 4);
    score_kernel<<<qgrid, 256>>>(x);

    dim3 sgrid(EE / 256, 8);
    scatter_kernel<<<sgrid, 256>>>(ep);

    dim3 ggrid((NN + 63) / 64, 4);
    gemm_kernel<<<ggrid, 256>>>(x, W);

    dim3 agrid((NN + 7) / 8, 8);
    gather_kernel<<<agrid, 256>>>(bias, (float*)d_out);
}

// round 4
// speedup vs baseline: 1.2861x; 1.1042x over previous
#include <cuda_runtime.h>
#include <cuda_fp16.h>

#define NN 50000
#define DD 64
#define EE 800000

// ---- scratch (device globals; no runtime allocation allowed) ----
__device__ __half2 g_hh[4ull * NN * 32];     // 25.6 MB  h = x@W per param set (fp16)
__device__ float   g_s[4 * NN];              // per-node src score  s_i = h_i . a_src
__device__ float   g_d[4 * NN];              // per-node dst score
__device__ int     g_cnt[8 * NN];            // per-(conv,node) incoming-edge count
__device__ int     g_ebuf[8ull * NN * 64];   // 102.4 MB  src-only records, 64 slots/node

// conv c (edge input order: tp_a,tp_b,tn_a,tn_b,dp_a,dp_b,dn_a,dn_b) -> output slot
__constant__ int c_omap[8] = {0, 1, 4, 5, 2, 3, 6, 7};

struct EdgePtrs { const int* e[8]; };

// ---------------------------------------------------------------------------
// Kernel 1: h = x @ W[p] (fp16 out) + fused per-row scores s,d + cnt zeroing.
// block = 256 (8 warps), 64 rows/block, warp -> 8 rows, lane -> cols {2l,2l+1}.
// grid = (782, 4).
// ---------------------------------------------------------------------------
__global__ void __launch_bounds__(256) gemm_kernel(const float* __restrict__ x,
                                                   const float* __restrict__ W,
                                                   const float* __restrict__ asrc,
                                                   const float* __restrict__ adst) {
    __shared__ float Ws[64 * 64];            // 16 KB
    __shared__ float xs[64 * 68];            // 17.4 KB (68-stride: float4-aligned + pad)
    const int p    = blockIdx.y;
    const int row0 = blockIdx.x * 64;
    const int tid  = threadIdx.x;

    // zero edge counters from the p==0 plane (782*256*2 = 400384 >= 400000)
    if (p == 0) {
        int z = blockIdx.x * 256 + tid;
        if (z < 8 * NN) g_cnt[z] = 0;
        int z2 = z + 200192;
        if (z2 < 8 * NN) g_cnt[z2] = 0;
    }

    {   // load W (1024 float4, coalesced)
        const float4* W4 = (const float4*)(W + p * 4096);
        float4* Ws4 = (float4*)Ws;
        Ws4[tid]       = W4[tid];
        Ws4[tid + 256] = W4[tid + 256];
        Ws4[tid + 512] = W4[tid + 512];
        Ws4[tid + 768] = W4[tid + 768];
    }
    // load 64 x-rows (float4, coalesced)
#pragma unroll
    for (int q = tid; q < 1024; q += 256) {
        int r = q >> 4, c4 = q & 15;
        int grow = row0 + r;
        float4 v = (grow < NN) ? ((const float4*)x)[(size_t)grow * 16 + c4]
                               : make_float4(0.f, 0.f, 0.f, 0.f);
        *(float4*)&xs[r * 68 + c4 * 4] = v;
    }
    __syncthreads();

    const int warp = tid >> 5, lane = tid & 31;
    const int r0 = warp * 8;
    float2 acc[8];
#pragma unroll
    for (int r = 0; r < 8; r++) acc[r] = make_float2(0.f, 0.f);

    const float2* Ws2 = (const float2*)Ws;
#pragma unroll 4
    for (int k = 0; k < 64; k += 4) {
        float2 w0 = Ws2[(k + 0) * 32 + lane];
        float2 w1 = Ws2[(k + 1) * 32 + lane];
        float2 w2 = Ws2[(k + 2) * 32 + lane];
        float2 w3 = Ws2[(k + 3) * 32 + lane];
#pragma unroll
        for (int r = 0; r < 8; r++) {
            float4 xv = *(const float4*)&xs[(r0 + r) * 68 + k];
            acc[r].x = fmaf(xv.x, w0.x, acc[r].x); acc[r].y = fmaf(xv.x, w0.y, acc[r].y);
            acc[r].x = fmaf(xv.y, w1.x, acc[r].x); acc[r].y = fmaf(xv.y, w1.y, acc[r].y);
            acc[r].x = fmaf(xv.z, w2.x, acc[r].x); acc[r].y = fmaf(xv.z, w2.y, acc[r].y);
            acc[r].x = fmaf(xv.w, w3.x, acc[r].x); acc[r].y = fmaf(xv.w, w3.y, acc[r].y);
        }
    }

    // fused scores: s = h.a_src, d = h.a_dst via in-warp butterfly reduce
    float2 av = ((const float2*)(asrc + p * 64))[lane];
    float2 bv = ((const float2*)(adst + p * 64))[lane];
    __half2* hp = g_hh + (size_t)p * NN * 32;

#pragma unroll
    for (int r = 0; r < 8; r++) {
        int grow = row0 + r0 + r;
        float sv = acc[r].x * av.x + acc[r].y * av.y;
        float dv = acc[r].x * bv.x + acc[r].y * bv.y;
#pragma unroll
        for (int off = 16; off; off >>= 1) {
            sv += __shfl_xor_sync(0xffffffffu, sv, off);
            dv += __shfl_xor_sync(0xffffffffu, dv, off);
        }
        if (grow < NN) {
            hp[(size_t)grow * 32 + lane] = __float22half2_rn(acc[r]);  // 128B/row
            if (lane == 0) { g_s[p * NN + grow] = sv; g_d[p * NN + grow] = dv; }
        }
    }
}

// ---------------------------------------------------------------------------
// Kernel 2: bucket every (non-self) edge by dst; record src only (4B).
// grid = (3125, 8), block = 256
// ---------------------------------------------------------------------------
__global__ void scatter_kernel(EdgePtrs ep) {
    const int c = blockIdx.y;
    const int r = blockIdx.x * blockDim.x + threadIdx.x;
    if (r >= EE) return;
    const int* __restrict__ e = ep.e[c];
    int src = __ldg(e + r);
    int dst = __ldg(e + EE + r);
    if (src == dst) return;                 // ref masks self edges to -1e9 -> weight 0
    int slot = atomicAdd(g_cnt + c * NN + dst, 1);
    if (slot < 64)
        g_ebuf[(((size_t)c * NN + dst) << 6) + slot] = src;
}

// ---------------------------------------------------------------------------
// Kernel 3: warp per (conv, node). Weights lane-parallel (MUFU exp), records
// broadcast via per-warp smem, h rows read as fp16, normalize at the end.
// grid = (6250, 8), block = 256.
// ---------------------------------------------------------------------------
__global__ void __launch_bounds__(256) gather_kernel(const float* __restrict__ bias,
                                                     float* __restrict__ out) {
    __shared__ int2 rec[8][64];
    const int c    = blockIdx.y;
    const int warp = threadIdx.x >> 5, lane = threadIdx.x & 31;
    const int i    = blockIdx.x * 8 + warp;
    if (i >= NN) return;
    const int p = c >> 1;
    const int o = c_omap[c];

    int n = g_cnt[c * NN + i];
    if (n > 64) n = 64;

    const int*   eb  = g_ebuf + (((size_t)c * NN + i) << 6);
    const float* sp  = g_s + p * NN;
    const float  d_i = __ldg(g_d + p * NN + i);

    float w1 = 0.f, w2 = 0.f;
    int   s1 = 0,   s2 = 0;
    if (lane < n) {
        s1 = __ldg(eb + lane);
        float t = __ldg(sp + s1) + d_i;
        t = t > 0.f ? t : 0.2f * t;
        w1 = __expf(t);
    }
    if (lane + 32 < n) {
        s2 = __ldg(eb + lane + 32);
        float t = __ldg(sp + s2) + d_i;
        t = t > 0.f ? t : 0.2f * t;
        w2 = __expf(t);
    }
    rec[warp][lane] = make_int2(s1, __float_as_int(w1));
    if (n > 32) rec[warp][lane + 32] = make_int2(s2, __float_as_int(w2));
    __syncwarp();

    float tself = __ldg(sp + i) + d_i;
    tself = tself > 0.f ? tself : 0.2f * tself;
    const float wself = __expf(tself);

    float wsum = w1 + w2;
#pragma unroll
    for (int off = 16; off; off >>= 1) wsum += __shfl_xor_sync(0xffffffffu, wsum, off);
    const float inv = 1.f / (wself + wsum);

    const __half2* __restrict__ h2 = g_hh;
    const size_t hbase = (size_t)p * NN;
    float2 hv = __half22float2(h2[(hbase + i) * 32 + lane]);
    float ax = wself * hv.x, ay = wself * hv.y;

#pragma unroll 4
    for (int k = 0; k < n; k++) {
        int2 rr = rec[warp][k];                               // LDS.64 broadcast
        float2 hh = __half22float2(h2[(hbase + rr.x) * 32 + lane]); // 128B row
        float wk = __int_as_float(rr.y);
        ax = fmaf(wk, hh.x, ax);
        ay = fmaf(wk, hh.y, ay);
    }

    float2 bb = ((const float2*)bias)[p * 32 + lane];
    ax = fmaxf(fmaf(ax, inv, bb.x), 0.f);
    ay = fmaxf(fmaf(ay, inv, bb.y), 0.f);
    ((float2*)out)[((size_t)o * NN + i) * 32 + lane] = make_float2(ax, ay);
}

// ---------------------------------------------------------------------------
extern "C" void kernel_launch(void* const* d_in, const int* in_sizes, int n_in,
                              void* d_out, int out_size) {
    (void)in_sizes; (void)n_in; (void)out_size;
    const float* x    = (const float*)d_in[8];
    const float* W    = (const float*)d_in[9];
    const float* asrc = (const float*)d_in[10];
    const float* adst = (const float*)d_in[11];
    const float* bias = (const float*)d_in[12];

    EdgePtrs ep;
    for (int i = 0; i < 8; i++) ep.e[i] = (const int*)d_in[i];

    dim3 ggrid((NN + 63) / 64, 4);
    gemm_kernel<<<ggrid, 256>>>(x, W, asrc, adst);

    dim3 sgrid(EE / 256, 8);
    scatter_kernel<<<sgrid, 256>>>(ep);

    dim3 agrid((NN + 7) / 8, 8);
    gather_kernel<<<agrid, 256>>>(bias, (float*)d_out);
}

// round 5
// speedup vs baseline: 1.3770x; 1.0706x over previous
#include <cuda_runtime.h>
#include <cuda_fp16.h>

#define NN 50000
#define DD 64
#define EE 800000

// ---- scratch (device globals; no runtime allocation allowed) ----
__device__ __half2 g_hh[4ull * NN * 32];     // 25.6 MB  h = x@W per param set (fp16)
__device__ float   g_s[4 * NN];              // per-node src score  s_i = h_i . a_src
__device__ float   g_d[4 * NN];              // per-node dst score
__device__ int     g_cnt[8 * NN];            // per-(conv,node) incoming-edge count
__device__ int     g_ebuf[8ull * NN * 64];   // 102.4 MB  src-only records, 64 slots/node

// conv c (edge input order: tp_a,tp_b,tn_a,tn_b,dp_a,dp_b,dn_a,dn_b) -> output slot
__constant__ int c_omap[8] = {0, 1, 4, 5, 2, 3, 6, 7};

struct EdgePtrs { const int* e[8]; };

// ---------------------------------------------------------------------------
// Kernel 0: zero the per-(conv,node) counters.  grid=391, block=1024.
// ---------------------------------------------------------------------------
__global__ void zero_kernel() {
    int z = blockIdx.x * blockDim.x + threadIdx.x;
    if (z < 8 * NN) g_cnt[z] = 0;
}

// ---------------------------------------------------------------------------
// Kernel 1: h = x @ W[p] (fp16 out) + fused per-row scores s,d.
// block = 256 (8 warps), 64 rows/block, warp -> 8 rows, lane -> cols {2l,2l+1}.
// grid = (782, 4).  Runs on a side stream, overlapped with scatter.
// ---------------------------------------------------------------------------
__global__ void __launch_bounds__(256) gemm_kernel(const float* __restrict__ x,
                                                   const float* __restrict__ W,
                                                   const float* __restrict__ asrc,
                                                   const float* __restrict__ adst) {
    __shared__ float Ws[64 * 64];            // 16 KB
    __shared__ float xs[64 * 68];            // 17.4 KB (68-stride: float4-aligned + pad)
    const int p    = blockIdx.y;
    const int row0 = blockIdx.x * 64;
    const int tid  = threadIdx.x;

    {   // load W (1024 float4, coalesced)
        const float4* W4 = (const float4*)(W + p * 4096);
        float4* Ws4 = (float4*)Ws;
        Ws4[tid]       = W4[tid];
        Ws4[tid + 256] = W4[tid + 256];
        Ws4[tid + 512] = W4[tid + 512];
        Ws4[tid + 768] = W4[tid + 768];
    }
    // load 64 x-rows (float4, coalesced)
#pragma unroll
    for (int q = tid; q < 1024; q += 256) {
        int r = q >> 4, c4 = q & 15;
        int grow = row0 + r;
        float4 v = (grow < NN) ? ((const float4*)x)[(size_t)grow * 16 + c4]
                               : make_float4(0.f, 0.f, 0.f, 0.f);
        *(float4*)&xs[r * 68 + c4 * 4] = v;
    }
    __syncthreads();

    const int warp = tid >> 5, lane = tid & 31;
    const int r0 = warp * 8;
    float2 acc[8];
#pragma unroll
    for (int r = 0; r < 8; r++) acc[r] = make_float2(0.f, 0.f);

    const float2* Ws2 = (const float2*)Ws;
#pragma unroll 4
    for (int k = 0; k < 64; k += 4) {
        float2 w0 = Ws2[(k + 0) * 32 + lane];
        float2 w1 = Ws2[(k + 1) * 32 + lane];
        float2 w2 = Ws2[(k + 2) * 32 + lane];
        float2 w3 = Ws2[(k + 3) * 32 + lane];
#pragma unroll
        for (int r = 0; r < 8; r++) {
            float4 xv = *(const float4*)&xs[(r0 + r) * 68 + k];
            acc[r].x = fmaf(xv.x, w0.x, acc[r].x); acc[r].y = fmaf(xv.x, w0.y, acc[r].y);
            acc[r].x = fmaf(xv.y, w1.x, acc[r].x); acc[r].y = fmaf(xv.y, w1.y, acc[r].y);
            acc[r].x = fmaf(xv.z, w2.x, acc[r].x); acc[r].y = fmaf(xv.z, w2.y, acc[r].y);
            acc[r].x = fmaf(xv.w, w3.x, acc[r].x); acc[r].y = fmaf(xv.w, w3.y, acc[r].y);
        }
    }

    // fused scores: s = h.a_src, d = h.a_dst via in-warp butterfly reduce
    float2 av = ((const float2*)(asrc + p * 64))[lane];
    float2 bv = ((const float2*)(adst + p * 64))[lane];
    __half2* hp = g_hh + (size_t)p * NN * 32;

#pragma unroll
    for (int r = 0; r < 8; r++) {
        int grow = row0 + r0 + r;
        float sv = acc[r].x * av.x + acc[r].y * av.y;
        float dv = acc[r].x * bv.x + acc[r].y * bv.y;
#pragma unroll
        for (int off = 16; off; off >>= 1) {
            sv += __shfl_xor_sync(0xffffffffu, sv, off);
            dv += __shfl_xor_sync(0xffffffffu, dv, off);
        }
        if (grow < NN) {
            hp[(size_t)grow * 32 + lane] = __float22half2_rn(acc[r]);  // 128B/row
            if (lane == 0) { g_s[p * NN + grow] = sv; g_d[p * NN + grow] = dv; }
        }
    }
}

// ---------------------------------------------------------------------------
// Kernel 2: bucket every (non-self) edge by dst; record src only (4B).
// 2 edges per thread via int2 loads.  grid = (1563, 8), block = 256.
// ---------------------------------------------------------------------------
__global__ void scatter_kernel(EdgePtrs ep) {
    const int c = blockIdx.y;
    const int r2 = blockIdx.x * blockDim.x + threadIdx.x;   // pair index
    if (r2 * 2 >= EE) return;
    const int* __restrict__ e = ep.e[c];
    int2 sv = __ldg((const int2*)e + r2);
    int2 dv = __ldg((const int2*)(e + EE) + r2);
    int* cnt = g_cnt + c * NN;
    const size_t cbase = ((size_t)c * NN) << 6;
    if (sv.x != dv.x) {
        int slot = atomicAdd(cnt + dv.x, 1);
        if (slot < 64) g_ebuf[cbase + ((size_t)dv.x << 6) + slot] = sv.x;
    }
    if (sv.y != dv.y) {
        int slot = atomicAdd(cnt + dv.y, 1);
        if (slot < 64) g_ebuf[cbase + ((size_t)dv.y << 6) + slot] = sv.y;
    }
}

// ---------------------------------------------------------------------------
// Kernel 3: warp per (conv, node). Weights lane-parallel (MUFU exp), records
// broadcast via per-warp smem, h rows read as fp16, normalize at the end.
// grid = (6250, 8), block = 256.
// ---------------------------------------------------------------------------
__global__ void __launch_bounds__(256) gather_kernel(const float* __restrict__ bias,
                                                     float* __restrict__ out) {
    __shared__ int2 rec[8][64];
    const int c    = blockIdx.y;
    const int warp = threadIdx.x >> 5, lane = threadIdx.x & 31;
    const int i    = blockIdx.x * 8 + warp;
    if (i >= NN) return;
    const int p = c >> 1;
    const int o = c_omap[c];

    int n = g_cnt[c * NN + i];
    if (n > 64) n = 64;

    const int*   eb  = g_ebuf + (((size_t)c * NN + i) << 6);
    const float* sp  = g_s + p * NN;
    const float  d_i = __ldg(g_d + p * NN + i);

    float w1 = 0.f, w2 = 0.f;
    int   s1 = 0,   s2 = 0;
    if (lane < n) {
        s1 = __ldg(eb + lane);
        float t = __ldg(sp + s1) + d_i;
        t = t > 0.f ? t : 0.2f * t;
        w1 = __expf(t);
    }
    if (lane + 32 < n) {
        s2 = __ldg(eb + lane + 32);
        float t = __ldg(sp + s2) + d_i;
        t = t > 0.f ? t : 0.2f * t;
        w2 = __expf(t);
    }
    rec[warp][lane] = make_int2(s1, __float_as_int(w1));
    if (n > 32) rec[warp][lane + 32] = make_int2(s2, __float_as_int(w2));
    __syncwarp();

    float tself = __ldg(sp + i) + d_i;
    tself = tself > 0.f ? tself : 0.2f * tself;
    const float wself = __expf(tself);

    float wsum = w1 + w2;
#pragma unroll
    for (int off = 16; off; off >>= 1) wsum += __shfl_xor_sync(0xffffffffu, wsum, off);
    const float inv = 1.f / (wself + wsum);

    const __half2* __restrict__ h2 = g_hh;
    const size_t hbase = (size_t)p * NN;
    float2 hv = __half22float2(h2[(hbase + i) * 32 + lane]);
    float ax = wself * hv.x, ay = wself * hv.y;

#pragma unroll 4
    for (int k = 0; k < n; k++) {
        int2 rr = rec[warp][k];                               // LDS.64 broadcast
        float2 hh = __half22float2(h2[(hbase + rr.x) * 32 + lane]); // 128B row
        float wk = __int_as_float(rr.y);
        ax = fmaf(wk, hh.x, ax);
        ay = fmaf(wk, hh.y, ay);
    }

    float2 bb = ((const float2*)bias)[p * 32 + lane];
    ax = fmaxf(fmaf(ax, inv, bb.x), 0.f);
    ay = fmaxf(fmaf(ay, inv, bb.y), 0.f);
    ((float2*)out)[((size_t)o * NN + i) * 32 + lane] = make_float2(ax, ay);
}

// ---------------------------------------------------------------------------
extern "C" void kernel_launch(void* const* d_in, const int* in_sizes, int n_in,
                              void* d_out, int out_size) {
    (void)in_sizes; (void)n_in; (void)out_size;
    const float* x    = (const float*)d_in[8];
    const float* W    = (const float*)d_in[9];
    const float* asrc = (const float*)d_in[10];
    const float* adst = (const float*)d_in[11];
    const float* bias = (const float*)d_in[12];

    EdgePtrs ep;
    for (int i = 0; i < 8; i++) ep.e[i] = (const int*)d_in[i];

    // one-time resources (created on the uncaptured correctness call; reused
    // identically on every call -> same captured work DAG every time)
    static cudaStream_t s2 = nullptr;
    static cudaEvent_t evFork = nullptr, evJoin = nullptr;
    if (!s2) {
        cudaStreamCreateWithFlags(&s2, cudaStreamNonBlocking);
        cudaEventCreateWithFlags(&evFork, cudaEventDisableTiming);
        cudaEventCreateWithFlags(&evJoin, cudaEventDisableTiming);
    }

    // fork: gemm (+scores) on side stream, scatter path on main stream
    cudaEventRecord(evFork, 0);
    cudaStreamWaitEvent(s2, evFork, 0);

    dim3 ggrid((NN + 63) / 64, 4);
    gemm_kernel<<<ggrid, 256, 0, s2>>>(x, W, asrc, adst);
    cudaEventRecord(evJoin, s2);

    zero_kernel<<<(8 * NN + 1023) / 1024, 1024>>>();
    dim3 sgrid((EE / 2 + 255) / 256, 8);
    scatter_kernel<<<sgrid, 256>>>(ep);

    // join: gather needs h/s/d (gemm) and buckets (scatter)
    cudaStreamWaitEvent(0, evJoin, 0);
    dim3 agrid((NN + 7) / 8, 8);
    gather_kernel<<<agrid, 256>>>(bias, (float*)d_out);
}